// round 3
// baseline (speedup 1.0000x reference)
#include <cuda_runtime.h>
#include <cuda_fp16.h>
#include <cstdint>

// ============================================================================
// Problem constants
// ============================================================================
#define M_TOTAL 8192   // B*S = 4*2048
#define DIN     2048
#define DOUT    2048
#define QDIV    358.4f // 448 * 0.8

// GEMM tiling (fp8: 1 byte/elem, BK=128 elems = one 128B SW128 row)
#define BM 128
#define BN 128
#define BK 128
#define STAGES 3
#define NIT (DIN / BK)   // 16

// ============================================================================
// Device-global scratch (allocation-free requirement)
// ============================================================================
__device__ unsigned g_amax_x_bits;
__device__ unsigned g_amax_w_bits;
__device__ float    g_sx, g_sw, g_inv_sx, g_inv_sw, g_out_scale;
__device__ __align__(128) uint8_t g_qx[(size_t)M_TOTAL * DIN];   // 16 MB e4m3
__device__ __align__(128) uint8_t g_qw[(size_t)DOUT * DIN];      //  4 MB e4m3

// ============================================================================
// Helpers
// ============================================================================
__device__ __forceinline__ uint32_t smem_to_u32(const void* p) {
    uint32_t a;
    asm("{ .reg .u64 t; cvta.to.shared.u64 t, %1; cvt.u32.u64 %0, t; }"
        : "=r"(a) : "l"(p));
    return a;
}

// fp32x2 -> packed e4m3x2 (RN, satfinite). low byte = lo, high byte = hi.
__device__ __forceinline__ uint16_t cvt_e4m3x2(float hi, float lo) {
    uint16_t r;
    asm("cvt.rn.satfinite.e4m3x2.f32 %0, %1, %2;" : "=h"(r) : "f"(hi), "f"(lo));
    return r;
}

#define CP_ASYNC_16(dst, src) \
    asm volatile("cp.async.cg.shared.global [%0], [%1], 16;" \
                 :: "r"(dst), "l"(src))
#define CP_ASYNC_COMMIT() asm volatile("cp.async.commit_group;")
#define CP_ASYNC_WAIT_1() asm volatile("cp.async.wait_group 1;")

#define LDSM_X4(r, addr) \
    asm volatile("ldmatrix.sync.aligned.m8n8.x4.shared.b16 {%0,%1,%2,%3}, [%4];" \
        : "=r"((r)[0]), "=r"((r)[1]), "=r"((r)[2]), "=r"((r)[3]) : "r"(addr))

// FP8 e4m3 MMA: D(16x8,f32) += A(16x32,e4m3) * B(32x8,e4m3)
__device__ __forceinline__ void mma16832(float* d, const uint32_t* a,
                                         const uint32_t* b) {
    asm volatile(
        "mma.sync.aligned.m16n8k32.row.col.f32.e4m3.e4m3.f32 "
        "{%0,%1,%2,%3}, {%4,%5,%6,%7}, {%8,%9}, {%0,%1,%2,%3};"
        : "+f"(d[0]), "+f"(d[1]), "+f"(d[2]), "+f"(d[3])
        : "r"(a[0]), "r"(a[1]), "r"(a[2]), "r"(a[3]), "r"(b[0]), "r"(b[1]));
}

// SW128 swizzle for 128-byte rows (byte offsets)
__device__ __forceinline__ uint32_t swz(uint32_t off) {
    return off ^ ((off >> 3) & 0x70);
}

// ============================================================================
// Kernel 0: zero the amax scratch
// ============================================================================
__global__ void init_kernel() {
    g_amax_x_bits = 0u;
    g_amax_w_bits = 0u;
}

// ============================================================================
// Kernel 1: amax reduction (atomicMax on positive-float bits, order-exact)
// ============================================================================
__global__ void amax_kernel(const float4* __restrict__ p, int n4, int which) {
    float m = 0.0f;
    for (int i = blockIdx.x * blockDim.x + threadIdx.x; i < n4;
         i += gridDim.x * blockDim.x) {
        float4 v = p[i];
        m = fmaxf(m, fmaxf(fmaxf(fabsf(v.x), fabsf(v.y)),
                           fmaxf(fabsf(v.z), fabsf(v.w))));
    }
    #pragma unroll
    for (int o = 16; o; o >>= 1)
        m = fmaxf(m, __shfl_xor_sync(0xFFFFFFFFu, m, o));
    if ((threadIdx.x & 31) == 0)
        atomicMax(which ? &g_amax_w_bits : &g_amax_x_bits, __float_as_uint(m));
}

// ============================================================================
// Kernel 2: compute scales (IEEE div once, matching reference exactly)
// ============================================================================
__global__ void scales_kernel() {
    float ax = __uint_as_float(g_amax_x_bits);
    float aw = __uint_as_float(g_amax_w_bits);
    float sx = ax / QDIV;
    float sw = fmaxf(ax, aw) / QDIV;  // shared scaling-manager history max
    g_sx = sx;
    g_sw = sw;
    g_inv_sx = 1.0f / sx;
    g_inv_sw = 1.0f / sw;
    g_out_scale = sx * sw;
}

// ============================================================================
// Kernel 3: quantize: x -> e4m3(x/s), raw e4m3 bytes out.
// div_cr: reciprocal-multiply + one FMA residual step == IEEE div for all but
// ~2^-40 of inputs; 3-mantissa-bit e4m3 RNE absorbs the rest.
// ============================================================================
__device__ __forceinline__ float div_cr(float x, float s, float inv) {
    float y = x * inv;
    float e = fmaf(-s, y, x);
    return fmaf(e, inv, y);
}

__global__ void quant_kernel(const float4* __restrict__ p, int n4, int is_w) {
    const float s   = is_w ? g_sw : g_sx;
    const float inv = is_w ? g_inv_sw : g_inv_sx;
    uint32_t* q = (uint32_t*)(is_w ? (void*)g_qw : (void*)g_qx);
    for (int i = blockIdx.x * blockDim.x + threadIdx.x; i < n4;
         i += gridDim.x * blockDim.x) {
        float4 v = p[i];
        float y0 = div_cr(v.x, s, inv);
        float y1 = div_cr(v.y, s, inv);
        float y2 = div_cr(v.z, s, inv);
        float y3 = div_cr(v.w, s, inv);
        uint32_t lo = cvt_e4m3x2(y1, y0);
        uint32_t hi = cvt_e4m3x2(y3, y2);
        q[i] = lo | (hi << 16);
    }
}

// ============================================================================
// Kernel 4: FP8 mma.sync GEMM.  out[m,n] = (sum_k qx[m,k]*qw[n,k])*osc + b[n]
// 128x128x128 CTA tile, 3-stage cp.async pipeline, SW128 swizzle,
// 8 warps 2(M)x4(N), warp tile 64x32, m16n8k32 e4m3 MMA.
// Fragment addressing note: treating e4m3 pairs as b16 elements makes the
// ldmatrix lane addressing byte-identical to the f16 m16n8k16 scheme.
// ============================================================================
#define STAGE_BYTES 32768                 // A 16KB + B 16KB
#define GEMM_SMEM_BYTES (STAGES * STAGE_BYTES)

__global__ __launch_bounds__(256) void gemm_kernel(
    float* __restrict__ out, const float* __restrict__ bias)
{
    extern __shared__ char smem[];
    const uint32_t sb = smem_to_u32(smem);
    const int tid  = threadIdx.x;
    const int lane = tid & 31;
    const int warp = tid >> 5;
    const int wm = warp >> 2;       // 0..1
    const int wn = warp & 3;        // 0..3
    const int nt = blockIdx.x;      // 0..15
    const int mt = blockIdx.y;      // 0..63

    const uint8_t* gA = g_qx + (size_t)mt * BM * DIN;
    const uint8_t* gB = g_qw + (size_t)nt * BN * DIN;

    // ---- per-thread cp.async chunk map: 4 chunks A + 4 chunks B per stage ----
    // chunk ch (0..1023): row = ch>>3, 16B col block = ch&7
    uint32_t dst_off[4];
    const char* srcA[4];
    const char* srcB[4];
    #pragma unroll
    for (int q = 0; q < 4; ++q) {
        int ch  = tid + q * 256;
        int row = ch >> 3;
        int cb  = (ch & 7) * 16;
        dst_off[q] = swz((uint32_t)(row * 128 + cb));
        srcA[q] = (const char*)(gA + (size_t)row * DIN) + cb;
        srcB[q] = (const char*)(gB + (size_t)row * DIN) + cb;
    }

    // ---- prologue: fill STAGES-1 stages ----
    int li = 0;
    #pragma unroll
    for (int s = 0; s < STAGES - 1; ++s) {
        uint32_t sA = sb + s * STAGE_BYTES;
        uint32_t sB = sA + 16384;
        #pragma unroll
        for (int q = 0; q < 4; ++q) {
            CP_ASYNC_16(sA + dst_off[q], srcA[q] + li * BK);
            CP_ASYNC_16(sB + dst_off[q], srcB[q] + li * BK);
        }
        CP_ASYNC_COMMIT();
        ++li;
    }
    CP_ASYNC_WAIT_1();
    __syncthreads();

    // ---- ldmatrix per-lane address components (b16-pair view of e4m3) ----
    const int rA = wm * 64 + (lane & 7) + ((lane >> 3) & 1) * 8;
    const uint32_t cA0 = ((lane >> 4) & 1) * 16;
    const uint32_t xrA = (uint32_t)((rA & 7) << 4);
    const int rB = wn * 32 + (lane & 7) + ((lane >> 4) & 1) * 8;
    const uint32_t cB0 = ((lane >> 3) & 1) * 16;
    const uint32_t xrB = (uint32_t)((rB & 7) << 4);

    float acc[4][4][4];
    #pragma unroll
    for (int i = 0; i < 4; ++i)
        #pragma unroll
        for (int j = 0; j < 4; ++j)
            #pragma unroll
            for (int r = 0; r < 4; ++r) acc[i][j][r] = 0.0f;

    // ---- main loop ----
    #pragma unroll 1
    for (int it = 0; it < NIT; ++it) {
        const int cur = it % STAGES;
        if (li < NIT) {
            const int nx = (it + STAGES - 1) % STAGES;
            uint32_t sA = sb + nx * STAGE_BYTES;
            uint32_t sB = sA + 16384;
            #pragma unroll
            for (int q = 0; q < 4; ++q) {
                CP_ASYNC_16(sA + dst_off[q], srcA[q] + li * BK);
                CP_ASYNC_16(sB + dst_off[q], srcB[q] + li * BK);
            }
            ++li;
        }
        CP_ASYNC_COMMIT();

        // compute on stage cur: 4 k-steps of 32 e4m3 (32 bytes) each
        const uint32_t stA = sb + cur * STAGE_BYTES;
        const uint32_t stB = stA + 16384;
        #pragma unroll
        for (int s = 0; s < 4; ++s) {
            uint32_t a[4][4];
            #pragma unroll
            for (int i = 0; i < 4; ++i) {
                uint32_t addr = stA + (uint32_t)((rA + i * 16) * 128)
                              + ((cA0 + s * 32) ^ xrA);
                LDSM_X4(a[i], addr);
            }
            uint32_t b[2][4];
            #pragma unroll
            for (int jj = 0; jj < 2; ++jj) {
                uint32_t addr = stB + (uint32_t)((rB + jj * 16) * 128)
                              + ((cB0 + s * 32) ^ xrB);
                LDSM_X4(b[jj], addr);
            }
            #pragma unroll
            for (int i = 0; i < 4; ++i)
                #pragma unroll
                for (int j = 0; j < 4; ++j)
                    mma16832(acc[i][j], a[i], b[j >> 1] + (j & 1) * 2);
        }

        CP_ASYNC_WAIT_1();
        __syncthreads();
    }

    // ---- epilogue: scale + bias, float2 stores ----
    const float osc = g_out_scale;
    const int m0 = mt * BM + wm * 64 + (lane >> 2);
    const int n0 = nt * BN + wn * 32 + (lane & 3) * 2;
    #pragma unroll
    for (int i = 0; i < 4; ++i) {
        #pragma unroll
        for (int j = 0; j < 4; ++j) {
            const int m = m0 + i * 16;
            const int n = n0 + j * 8;
            const float b0 = __ldg(&bias[n]);
            const float b1 = __ldg(&bias[n + 1]);
            float2 v0, v1;
            v0.x = fmaf(acc[i][j][0], osc, b0);
            v0.y = fmaf(acc[i][j][1], osc, b1);
            v1.x = fmaf(acc[i][j][2], osc, b0);
            v1.y = fmaf(acc[i][j][3], osc, b1);
            *(float2*)&out[(size_t)m * DOUT + n]       = v0;
            *(float2*)&out[(size_t)(m + 8) * DOUT + n] = v1;
        }
    }
}

// ============================================================================
// kernel_launch
// ============================================================================
extern "C" void kernel_launch(void* const* d_in, const int* in_sizes, int n_in,
                              void* d_out, int out_size) {
    const float* x    = (const float*)d_in[0];   // [4,2048,2048]
    const float* w    = (const float*)d_in[1];   // [2048,2048]
    const float* bias = (const float*)d_in[2];   // [2048]
    float* out = (float*)d_out;

    static int smem_set = 0;
    if (!smem_set) {
        cudaFuncSetAttribute(gemm_kernel,
                             cudaFuncAttributeMaxDynamicSharedMemorySize,
                             GEMM_SMEM_BYTES);
        smem_set = 1;
    }

    const int nx4 = (M_TOTAL * DIN) / 4;  // 4194304
    const int nw4 = (DOUT * DIN) / 4;     // 1048576

    init_kernel<<<1, 1>>>();
    amax_kernel<<<1024, 256>>>((const float4*)x, nx4, 0);
    amax_kernel<<<512,  256>>>((const float4*)w, nw4, 1);
    scales_kernel<<<1, 1>>>();
    quant_kernel<<<4096, 256>>>((const float4*)x, nx4, 0);
    quant_kernel<<<1024, 256>>>((const float4*)w, nw4, 1);

    dim3 grid(DOUT / BN, M_TOTAL / BM);  // (16, 64)
    gemm_kernel<<<grid, 256, GEMM_SMEM_BYTES>>>(out, bias);
}

// round 4
// speedup vs baseline: 1.0881x; 1.0881x over previous
#include <cuda_runtime.h>
#include <cuda_fp16.h>
#include <cstdint>

// ============================================================================
// Problem constants
// ============================================================================
#define M_TOTAL 8192   // B*S = 4*2048
#define DIN     2048
#define DOUT    2048
#define QDIV    358.4f // 448 * 0.8

// GEMM tiling (f16 carrier): 128x256 CTA tile, BK=64, 3-stage pipeline
#define BM 128
#define BN 256
#define BK 64
#define STAGES 3
#define NIT (DIN / BK)   // 32

// ============================================================================
// Device-global scratch (allocation-free requirement)
// ============================================================================
__device__ unsigned g_amax_x_bits;
__device__ unsigned g_amax_w_bits;
// fp8-rounded values stored as f16 (exact: e4m3 subset of f16)
__device__ __align__(128) __half g_qx[(size_t)M_TOTAL * DIN];   // 32 MB
__device__ __align__(128) __half g_qw[(size_t)DOUT * DIN];      //  8 MB

// ============================================================================
// Helpers
// ============================================================================
__device__ __forceinline__ uint32_t smem_to_u32(const void* p) {
    uint32_t a;
    asm("{ .reg .u64 t; cvta.to.shared.u64 t, %1; cvt.u32.u64 %0, t; }"
        : "=r"(a) : "l"(p));
    return a;
}

// fp32x2 -> packed e4m3x2 (RN, satfinite). low byte = lo, high byte = hi.
__device__ __forceinline__ uint16_t cvt_e4m3x2(float hi, float lo) {
    uint16_t r;
    asm("cvt.rn.satfinite.e4m3x2.f32 %0, %1, %2;" : "=h"(r) : "f"(hi), "f"(lo));
    return r;
}

// packed e4m3x2 -> f16x2 (exact)
__device__ __forceinline__ uint32_t cvt_f16x2_from_e4m3x2(uint16_t e) {
    uint32_t r;
    asm("cvt.rn.f16x2.e4m3x2 %0, %1;" : "=r"(r) : "h"(e));
    return r;
}

#define CP_ASYNC_16(dst, src) \
    asm volatile("cp.async.cg.shared.global [%0], [%1], 16;" \
                 :: "r"(dst), "l"(src))
#define CP_ASYNC_COMMIT() asm volatile("cp.async.commit_group;")
#define CP_ASYNC_WAIT_1() asm volatile("cp.async.wait_group 1;")

#define LDSM_X4(r, addr) \
    asm volatile("ldmatrix.sync.aligned.m8n8.x4.shared.b16 {%0,%1,%2,%3}, [%4];" \
        : "=r"((r)[0]), "=r"((r)[1]), "=r"((r)[2]), "=r"((r)[3]) : "r"(addr))

__device__ __forceinline__ void mma16816(float* d, const uint32_t* a,
                                         const uint32_t* b) {
    asm volatile(
        "mma.sync.aligned.m16n8k16.row.col.f32.f16.f16.f32 "
        "{%0,%1,%2,%3}, {%4,%5,%6,%7}, {%8,%9}, {%0,%1,%2,%3};"
        : "+f"(d[0]), "+f"(d[1]), "+f"(d[2]), "+f"(d[3])
        : "r"(a[0]), "r"(a[1]), "r"(a[2]), "r"(a[3]), "r"(b[0]), "r"(b[1]));
}

// SW128 swizzle for 128-byte rows (byte offsets)
__device__ __forceinline__ uint32_t swz(uint32_t off) {
    return off ^ ((off >> 3) & 0x70);
}

// div via reciprocal + one FMA residual refinement (== IEEE div for all but
// ~2^-40 of inputs; 3-mantissa-bit e4m3 RNE absorbs the rest)
__device__ __forceinline__ float div_cr(float x, float s, float inv) {
    float y = x * inv;
    float e = fmaf(-s, y, x);
    return fmaf(e, inv, y);
}

// ============================================================================
// Kernel 0: zero the amax scratch
// ============================================================================
__global__ void init_kernel() {
    g_amax_x_bits = 0u;
    g_amax_w_bits = 0u;
}

// ============================================================================
// Kernel 1: fused amax over x (blocks [0,1024)) and w (blocks [1024,1536))
// atomicMax on positive-float bits is order-exact.
// ============================================================================
__global__ void amax_kernel(const float4* __restrict__ x,
                            const float4* __restrict__ w) {
    const bool is_w = blockIdx.x >= 1024;
    const float4* p = is_w ? w : x;
    const int n4 = is_w ? (DOUT * DIN / 4) : (M_TOTAL * DIN / 4);
    const int nblk = is_w ? 512 : 1024;
    const int b0 = is_w ? 1024 : 0;
    float m = 0.0f;
    for (int i = (blockIdx.x - b0) * blockDim.x + threadIdx.x; i < n4;
         i += nblk * blockDim.x) {
        float4 v = p[i];
        m = fmaxf(m, fmaxf(fmaxf(fabsf(v.x), fabsf(v.y)),
                           fmaxf(fabsf(v.z), fabsf(v.w))));
    }
    #pragma unroll
    for (int o = 16; o; o >>= 1)
        m = fmaxf(m, __shfl_xor_sync(0xFFFFFFFFu, m, o));
    if ((threadIdx.x & 31) == 0)
        atomicMax(is_w ? &g_amax_w_bits : &g_amax_x_bits, __float_as_uint(m));
}

// ============================================================================
// Kernel 2: fused quantize x (blocks [0,4096)) and w (blocks [4096,5120)).
// Scales computed inline from the amax globals (deterministic recompute).
// Output: e4m3-rounded value stored exactly as f16.
// ============================================================================
__global__ void quant_kernel(const float4* __restrict__ x,
                             const float4* __restrict__ w) {
    const float ax = __uint_as_float(g_amax_x_bits);
    const float aw = __uint_as_float(g_amax_w_bits);
    const bool is_w = blockIdx.x >= 4096;
    const float s   = is_w ? (fmaxf(ax, aw) / QDIV) : (ax / QDIV);
    const float inv = 1.0f / s;
    const float4* p = is_w ? w : x;
    uint2* q = (uint2*)(is_w ? (void*)g_qw : (void*)g_qx);
    const int n4 = is_w ? (DOUT * DIN / 4) : (M_TOTAL * DIN / 4);
    const int nblk = is_w ? 1024 : 4096;
    const int b0 = is_w ? 4096 : 0;
    for (int i = (blockIdx.x - b0) * blockDim.x + threadIdx.x; i < n4;
         i += nblk * blockDim.x) {
        float4 v = p[i];
        float y0 = div_cr(v.x, s, inv);
        float y1 = div_cr(v.y, s, inv);
        float y2 = div_cr(v.z, s, inv);
        float y3 = div_cr(v.w, s, inv);
        uint2 o;
        o.x = cvt_f16x2_from_e4m3x2(cvt_e4m3x2(y1, y0));
        o.y = cvt_f16x2_from_e4m3x2(cvt_e4m3x2(y3, y2));
        q[i] = o;
    }
}

// ============================================================================
// Kernel 3: f16 HMMA GEMM. out[m,n] = (sum_k qx[m,k]*qw[n,k])*osc + bias[n]
// 128x256x64 CTA tile, 3-stage cp.async, SW128 swizzle,
// 8 warps 2(M)x4(N), warp tile 64x64, m16n8k16.
// ============================================================================
#define A_STAGE_BYTES 16384               // 128 rows x 128B
#define B_STAGE_BYTES 32768               // 256 rows x 128B
#define STAGE_BYTES (A_STAGE_BYTES + B_STAGE_BYTES)   // 49152
#define GEMM_SMEM_BYTES (STAGES * STAGE_BYTES)        // 147456

__global__ __launch_bounds__(256, 1) void gemm_kernel(
    float* __restrict__ out, const float* __restrict__ bias)
{
    extern __shared__ char smem[];
    const uint32_t sb = smem_to_u32(smem);
    const int tid  = threadIdx.x;
    const int lane = tid & 31;
    const int warp = tid >> 5;
    const int wm = warp >> 2;       // 0..1
    const int wn = warp & 3;        // 0..3
    const int nt = blockIdx.x;      // 0..7
    const int mt = blockIdx.y;      // 0..63

    const __half* gA = g_qx + (size_t)mt * BM * DIN;
    const __half* gB = g_qw + (size_t)nt * BN * DIN;

    // ---- cp.async chunk maps: A 1024 chunks (4/thr), B 2048 chunks (8/thr) ----
    uint32_t dstA[4], dstB[8];
    const char* srcA[4];
    const char* srcB[8];
    #pragma unroll
    for (int q = 0; q < 4; ++q) {
        int ch  = tid + q * 256;
        int row = ch >> 3;
        int cb  = (ch & 7) * 16;
        dstA[q] = swz((uint32_t)(row * 128 + cb));
        srcA[q] = (const char*)(gA + (size_t)row * DIN) + cb;
    }
    #pragma unroll
    for (int q = 0; q < 8; ++q) {
        int ch  = tid + q * 256;
        int row = ch >> 3;
        int cb  = (ch & 7) * 16;
        dstB[q] = (uint32_t)A_STAGE_BYTES + swz((uint32_t)(row * 128 + cb));
        srcB[q] = (const char*)(gB + (size_t)row * DIN) + cb;
    }

    // ---- prologue: fill STAGES-1 stages ----
    int li = 0;
    #pragma unroll
    for (int s = 0; s < STAGES - 1; ++s) {
        uint32_t st = sb + s * STAGE_BYTES;
        #pragma unroll
        for (int q = 0; q < 4; ++q)
            CP_ASYNC_16(st + dstA[q], srcA[q] + li * (BK * 2));
        #pragma unroll
        for (int q = 0; q < 8; ++q)
            CP_ASYNC_16(st + dstB[q], srcB[q] + li * (BK * 2));
        CP_ASYNC_COMMIT();
        ++li;
    }
    CP_ASYNC_WAIT_1();
    __syncthreads();

    // ---- ldmatrix per-lane address components ----
    const int rA = wm * 64 + (lane & 7) + ((lane >> 3) & 1) * 8;
    const uint32_t cA0 = ((lane >> 4) & 1) * 16;
    const uint32_t xrA = (uint32_t)((rA & 7) << 4);
    const int rB = wn * 64 + (lane & 7) + ((lane >> 4) & 1) * 8;
    const uint32_t cB0 = ((lane >> 3) & 1) * 16;
    const uint32_t xrB = (uint32_t)((rB & 7) << 4);

    float acc[4][8][4];
    #pragma unroll
    for (int i = 0; i < 4; ++i)
        #pragma unroll
        for (int j = 0; j < 8; ++j)
            #pragma unroll
            for (int r = 0; r < 4; ++r) acc[i][j][r] = 0.0f;

    // ---- main loop ----
    #pragma unroll 1
    for (int it = 0; it < NIT; ++it) {
        const int cur = it % STAGES;
        if (li < NIT) {
            const int nx = (it + STAGES - 1) % STAGES;
            uint32_t st = sb + nx * STAGE_BYTES;
            #pragma unroll
            for (int q = 0; q < 4; ++q)
                CP_ASYNC_16(st + dstA[q], srcA[q] + li * (BK * 2));
            #pragma unroll
            for (int q = 0; q < 8; ++q)
                CP_ASYNC_16(st + dstB[q], srcB[q] + li * (BK * 2));
            ++li;
        }
        CP_ASYNC_COMMIT();

        // compute on stage cur: 4 k16 steps
        const uint32_t stA = sb + cur * STAGE_BYTES;
        const uint32_t stB = stA + A_STAGE_BYTES;
        #pragma unroll
        for (int s = 0; s < 4; ++s) {
            uint32_t a[4][4];
            #pragma unroll
            for (int i = 0; i < 4; ++i) {
                uint32_t addr = stA + (uint32_t)((rA + i * 16) * 128)
                              + ((cA0 + s * 32) ^ xrA);
                LDSM_X4(a[i], addr);
            }
            uint32_t b[4][4];
            #pragma unroll
            for (int jj = 0; jj < 4; ++jj) {
                uint32_t addr = stB + (uint32_t)((rB + jj * 16) * 128)
                              + ((cB0 + s * 32) ^ xrB);
                LDSM_X4(b[jj], addr);
            }
            #pragma unroll
            for (int i = 0; i < 4; ++i)
                #pragma unroll
                for (int j = 0; j < 8; ++j)
                    mma16816(acc[i][j], a[i], b[j >> 1] + (j & 1) * 2);
        }

        CP_ASYNC_WAIT_1();
        __syncthreads();
    }

    // ---- epilogue: osc from amax globals (deterministic), scale + bias ----
    const float ax = __uint_as_float(g_amax_x_bits);
    const float aw = __uint_as_float(g_amax_w_bits);
    const float osc = (ax / QDIV) * (fmaxf(ax, aw) / QDIV);
    const int m0 = mt * BM + wm * 64 + (lane >> 2);
    const int n0 = nt * BN + wn * 64 + (lane & 3) * 2;
    #pragma unroll
    for (int i = 0; i < 4; ++i) {
        #pragma unroll
        for (int j = 0; j < 8; ++j) {
            const int m = m0 + i * 16;
            const int n = n0 + j * 8;
            const float b0 = __ldg(&bias[n]);
            const float b1 = __ldg(&bias[n + 1]);
            float2 v0, v1;
            v0.x = fmaf(acc[i][j][0], osc, b0);
            v0.y = fmaf(acc[i][j][1], osc, b1);
            v1.x = fmaf(acc[i][j][2], osc, b0);
            v1.y = fmaf(acc[i][j][3], osc, b1);
            *(float2*)&out[(size_t)m * DOUT + n]       = v0;
            *(float2*)&out[(size_t)(m + 8) * DOUT + n] = v1;
        }
    }
}

// ============================================================================
// kernel_launch: 4 launches (init, amax, quant, gemm)
// ============================================================================
extern "C" void kernel_launch(void* const* d_in, const int* in_sizes, int n_in,
                              void* d_out, int out_size) {
    const float* x    = (const float*)d_in[0];   // [4,2048,2048]
    const float* w    = (const float*)d_in[1];   // [2048,2048]
    const float* bias = (const float*)d_in[2];   // [2048]
    float* out = (float*)d_out;

    static int smem_set = 0;
    if (!smem_set) {
        cudaFuncSetAttribute(gemm_kernel,
                             cudaFuncAttributeMaxDynamicSharedMemorySize,
                             GEMM_SMEM_BYTES);
        smem_set = 1;
    }

    init_kernel<<<1, 1>>>();
    amax_kernel<<<1536, 256>>>((const float4*)x, (const float4*)w);
    quant_kernel<<<5120, 256>>>((const float4*)x, (const float4*)w);

    dim3 grid(DOUT / BN, M_TOTAL / BM);  // (8, 64)
    gemm_kernel<<<grid, 256, GEMM_SMEM_BYTES>>>(out, bias);
}

// round 5
// speedup vs baseline: 1.0985x; 1.0095x over previous
#include <cuda_runtime.h>
#include <cuda_fp16.h>
#include <cstdint>

// ============================================================================
// Problem constants
// ============================================================================
#define M_TOTAL 8192   // B*S = 4*2048
#define DIN     2048
#define DOUT    2048
#define QDIV    358.4f // 448 * 0.8

// GEMM tiling (f16 carrier): 128x256 CTA tile, BK=64, 3-stage, 512 threads
#define BM 128
#define BN 256
#define BK 64
#define STAGES 3
#define NIT (DIN / BK)   // 32

// ============================================================================
// Device-global scratch (allocation-free requirement)
// ============================================================================
__device__ unsigned g_amax_x_bits;
__device__ unsigned g_amax_w_bits;
// fp8-rounded values stored as f16 (exact: e4m3 subset of f16)
__device__ __align__(128) __half g_qx[(size_t)M_TOTAL * DIN];   // 32 MB
__device__ __align__(128) __half g_qw[(size_t)DOUT * DIN];      //  8 MB

// ============================================================================
// Helpers
// ============================================================================
__device__ __forceinline__ uint32_t smem_to_u32(const void* p) {
    uint32_t a;
    asm("{ .reg .u64 t; cvta.to.shared.u64 t, %1; cvt.u32.u64 %0, t; }"
        : "=r"(a) : "l"(p));
    return a;
}

// fp32x2 -> packed e4m3x2 (RN, satfinite). low byte = lo, high byte = hi.
__device__ __forceinline__ uint16_t cvt_e4m3x2(float hi, float lo) {
    uint16_t r;
    asm("cvt.rn.satfinite.e4m3x2.f32 %0, %1, %2;" : "=h"(r) : "f"(hi), "f"(lo));
    return r;
}

// packed e4m3x2 -> f16x2 (exact)
__device__ __forceinline__ uint32_t cvt_f16x2_from_e4m3x2(uint16_t e) {
    uint32_t r;
    asm("cvt.rn.f16x2.e4m3x2 %0, %1;" : "=r"(r) : "h"(e));
    return r;
}

#define CP_ASYNC_16(dst, src) \
    asm volatile("cp.async.cg.shared.global [%0], [%1], 16;" \
                 :: "r"(dst), "l"(src))
#define CP_ASYNC_COMMIT() asm volatile("cp.async.commit_group;")
#define CP_ASYNC_WAIT_1() asm volatile("cp.async.wait_group 1;")

#define LDSM_X4(r, addr) \
    asm volatile("ldmatrix.sync.aligned.m8n8.x4.shared.b16 {%0,%1,%2,%3}, [%4];" \
        : "=r"((r)[0]), "=r"((r)[1]), "=r"((r)[2]), "=r"((r)[3]) : "r"(addr))

__device__ __forceinline__ void mma16816(float* d, const uint32_t* a,
                                         const uint32_t* b) {
    asm volatile(
        "mma.sync.aligned.m16n8k16.row.col.f32.f16.f16.f32 "
        "{%0,%1,%2,%3}, {%4,%5,%6,%7}, {%8,%9}, {%0,%1,%2,%3};"
        : "+f"(d[0]), "+f"(d[1]), "+f"(d[2]), "+f"(d[3])
        : "r"(a[0]), "r"(a[1]), "r"(a[2]), "r"(a[3]), "r"(b[0]), "r"(b[1]));
}

// SW128 swizzle for 128-byte rows (byte offsets)
__device__ __forceinline__ uint32_t swz(uint32_t off) {
    return off ^ ((off >> 3) & 0x70);
}

// div via reciprocal + one FMA residual refinement (== IEEE div for all but
// ~2^-40 of inputs; 3-mantissa-bit e4m3 RNE absorbs the rest)
__device__ __forceinline__ float div_cr(float x, float s, float inv) {
    float y = x * inv;
    float e = fmaf(-s, y, x);
    return fmaf(e, inv, y);
}

// ============================================================================
// Kernel 0: zero the amax scratch
// ============================================================================
__global__ void init_kernel() {
    g_amax_x_bits = 0u;
    g_amax_w_bits = 0u;
}

// ============================================================================
// Kernel 1: fused amax over x (blocks [0,1024)) and w (blocks [1024,1536))
// atomicMax on positive-float bits is order-exact.
// ============================================================================
__global__ void amax_kernel(const float4* __restrict__ x,
                            const float4* __restrict__ w) {
    const bool is_w = blockIdx.x >= 1024;
    const float4* p = is_w ? w : x;
    const int n4 = is_w ? (DOUT * DIN / 4) : (M_TOTAL * DIN / 4);
    const int nblk = is_w ? 512 : 1024;
    const int b0 = is_w ? 1024 : 0;
    float m = 0.0f;
    for (int i = (blockIdx.x - b0) * blockDim.x + threadIdx.x; i < n4;
         i += nblk * blockDim.x) {
        float4 v = p[i];
        m = fmaxf(m, fmaxf(fmaxf(fabsf(v.x), fabsf(v.y)),
                           fmaxf(fabsf(v.z), fabsf(v.w))));
    }
    #pragma unroll
    for (int o = 16; o; o >>= 1)
        m = fmaxf(m, __shfl_xor_sync(0xFFFFFFFFu, m, o));
    if ((threadIdx.x & 31) == 0)
        atomicMax(is_w ? &g_amax_w_bits : &g_amax_x_bits, __float_as_uint(m));
}

// ============================================================================
// Kernel 2: fused quantize x (blocks [0,4096)) and w (blocks [4096,5120)).
// Scales computed inline from the amax globals (deterministic recompute).
// Output: e4m3-rounded value stored exactly as f16.
// ============================================================================
__global__ void quant_kernel(const float4* __restrict__ x,
                             const float4* __restrict__ w) {
    const float ax = __uint_as_float(g_amax_x_bits);
    const float aw = __uint_as_float(g_amax_w_bits);
    const bool is_w = blockIdx.x >= 4096;
    const float s   = is_w ? (fmaxf(ax, aw) / QDIV) : (ax / QDIV);
    const float inv = 1.0f / s;
    const float4* p = is_w ? w : x;
    uint2* q = (uint2*)(is_w ? (void*)g_qw : (void*)g_qx);
    const int n4 = is_w ? (DOUT * DIN / 4) : (M_TOTAL * DIN / 4);
    const int nblk = is_w ? 1024 : 4096;
    const int b0 = is_w ? 4096 : 0;
    for (int i = (blockIdx.x - b0) * blockDim.x + threadIdx.x; i < n4;
         i += nblk * blockDim.x) {
        float4 v = p[i];
        float y0 = div_cr(v.x, s, inv);
        float y1 = div_cr(v.y, s, inv);
        float y2 = div_cr(v.z, s, inv);
        float y3 = div_cr(v.w, s, inv);
        uint2 o;
        o.x = cvt_f16x2_from_e4m3x2(cvt_e4m3x2(y1, y0));
        o.y = cvt_f16x2_from_e4m3x2(cvt_e4m3x2(y3, y2));
        q[i] = o;
    }
}

// ============================================================================
// Kernel 3: f16 HMMA GEMM. out[m,n] = (sum_k qx[m,k]*qw[n,k])*osc + bias[n]
// 128x256x64 CTA tile, 3-stage cp.async, SW128 swizzle,
// 16 warps 2(M)x8(N), warp tile 64x32, m16n8k16. 512 threads.
// ============================================================================
#define A_STAGE_BYTES 16384               // 128 rows x 128B
#define B_STAGE_BYTES 32768               // 256 rows x 128B
#define STAGE_BYTES (A_STAGE_BYTES + B_STAGE_BYTES)   // 49152
#define GEMM_SMEM_BYTES (STAGES * STAGE_BYTES)        // 147456

__global__ __launch_bounds__(512, 1) void gemm_kernel(
    float* __restrict__ out, const float* __restrict__ bias)
{
    extern __shared__ char smem[];
    const uint32_t sb = smem_to_u32(smem);
    const int tid  = threadIdx.x;
    const int lane = tid & 31;
    const int warp = tid >> 5;
    const int wm = warp >> 3;       // 0..1
    const int wn = warp & 7;        // 0..7
    const int nt = blockIdx.x;      // 0..7
    const int mt = blockIdx.y;      // 0..63

    const __half* gA = g_qx + (size_t)mt * BM * DIN;
    const __half* gB = g_qw + (size_t)nt * BN * DIN;

    // ---- cp.async chunk maps: A 1024 chunks (2/thr), B 2048 chunks (4/thr) ----
    uint32_t dstA[2], dstB[4];
    const char* srcA[2];
    const char* srcB[4];
    #pragma unroll
    for (int q = 0; q < 2; ++q) {
        int ch  = tid + q * 512;
        int row = ch >> 3;
        int cb  = (ch & 7) * 16;
        dstA[q] = swz((uint32_t)(row * 128 + cb));
        srcA[q] = (const char*)(gA + (size_t)row * DIN) + cb;
    }
    #pragma unroll
    for (int q = 0; q < 4; ++q) {
        int ch  = tid + q * 512;
        int row = ch >> 3;
        int cb  = (ch & 7) * 16;
        dstB[q] = (uint32_t)A_STAGE_BYTES + swz((uint32_t)(row * 128 + cb));
        srcB[q] = (const char*)(gB + (size_t)row * DIN) + cb;
    }

    // ---- prologue: fill STAGES-1 stages ----
    int li = 0;
    #pragma unroll
    for (int s = 0; s < STAGES - 1; ++s) {
        uint32_t st = sb + s * STAGE_BYTES;
        #pragma unroll
        for (int q = 0; q < 2; ++q)
            CP_ASYNC_16(st + dstA[q], srcA[q] + li * (BK * 2));
        #pragma unroll
        for (int q = 0; q < 4; ++q)
            CP_ASYNC_16(st + dstB[q], srcB[q] + li * (BK * 2));
        CP_ASYNC_COMMIT();
        ++li;
    }
    CP_ASYNC_WAIT_1();
    __syncthreads();

    // ---- ldmatrix per-lane address components ----
    const int rA = wm * 64 + (lane & 7) + ((lane >> 3) & 1) * 8;
    const uint32_t cA0 = ((lane >> 4) & 1) * 16;
    const uint32_t xrA = (uint32_t)((rA & 7) << 4);
    const int rB = wn * 32 + (lane & 7) + ((lane >> 4) & 1) * 8;
    const uint32_t cB0 = ((lane >> 3) & 1) * 16;
    const uint32_t xrB = (uint32_t)((rB & 7) << 4);

    float acc[4][4][4];
    #pragma unroll
    for (int i = 0; i < 4; ++i)
        #pragma unroll
        for (int j = 0; j < 4; ++j)
            #pragma unroll
            for (int r = 0; r < 4; ++r) acc[i][j][r] = 0.0f;

    // ---- main loop ----
    #pragma unroll 1
    for (int it = 0; it < NIT; ++it) {
        const int cur = it % STAGES;
        if (li < NIT) {
            const int nx = (it + STAGES - 1) % STAGES;
            uint32_t st = sb + nx * STAGE_BYTES;
            #pragma unroll
            for (int q = 0; q < 2; ++q)
                CP_ASYNC_16(st + dstA[q], srcA[q] + li * (BK * 2));
            #pragma unroll
            for (int q = 0; q < 4; ++q)
                CP_ASYNC_16(st + dstB[q], srcB[q] + li * (BK * 2));
            ++li;
        }
        CP_ASYNC_COMMIT();

        // compute on stage cur: 4 k16 steps
        const uint32_t stA = sb + cur * STAGE_BYTES;
        const uint32_t stB = stA + A_STAGE_BYTES;
        #pragma unroll
        for (int s = 0; s < 4; ++s) {
            uint32_t a[4][4];
            #pragma unroll
            for (int i = 0; i < 4; ++i) {
                uint32_t addr = stA + (uint32_t)((rA + i * 16) * 128)
                              + ((cA0 + s * 32) ^ xrA);
                LDSM_X4(a[i], addr);
            }
            uint32_t b[2][4];
            #pragma unroll
            for (int jj = 0; jj < 2; ++jj) {
                uint32_t addr = stB + (uint32_t)((rB + jj * 16) * 128)
                              + ((cB0 + s * 32) ^ xrB);
                LDSM_X4(b[jj], addr);
            }
            #pragma unroll
            for (int i = 0; i < 4; ++i)
                #pragma unroll
                for (int j = 0; j < 4; ++j)
                    mma16816(acc[i][j], a[i], b[j >> 1] + (j & 1) * 2);
        }

        CP_ASYNC_WAIT_1();
        __syncthreads();
    }

    // ---- epilogue: osc from amax globals (deterministic), scale + bias ----
    const float ax = __uint_as_float(g_amax_x_bits);
    const float aw = __uint_as_float(g_amax_w_bits);
    const float osc = (ax / QDIV) * (fmaxf(ax, aw) / QDIV);
    const int m0 = mt * BM + wm * 64 + (lane >> 2);
    const int n0 = nt * BN + wn * 32 + (lane & 3) * 2;
    #pragma unroll
    for (int i = 0; i < 4; ++i) {
        #pragma unroll
        for (int j = 0; j < 4; ++j) {
            const int m = m0 + i * 16;
            const int n = n0 + j * 8;
            const float b0 = __ldg(&bias[n]);
            const float b1 = __ldg(&bias[n + 1]);
            float2 v0, v1;
            v0.x = fmaf(acc[i][j][0], osc, b0);
            v0.y = fmaf(acc[i][j][1], osc, b1);
            v1.x = fmaf(acc[i][j][2], osc, b0);
            v1.y = fmaf(acc[i][j][3], osc, b1);
            *(float2*)&out[(size_t)m * DOUT + n]       = v0;
            *(float2*)&out[(size_t)(m + 8) * DOUT + n] = v1;
        }
    }
}

// ============================================================================
// kernel_launch: 4 launches (init, amax, quant, gemm)
// ============================================================================
extern "C" void kernel_launch(void* const* d_in, const int* in_sizes, int n_in,
                              void* d_out, int out_size) {
    const float* x    = (const float*)d_in[0];   // [4,2048,2048]
    const float* w    = (const float*)d_in[1];   // [2048,2048]
    const float* bias = (const float*)d_in[2];   // [2048]
    float* out = (float*)d_out;

    static int smem_set = 0;
    if (!smem_set) {
        cudaFuncSetAttribute(gemm_kernel,
                             cudaFuncAttributeMaxDynamicSharedMemorySize,
                             GEMM_SMEM_BYTES);
        smem_set = 1;
    }

    init_kernel<<<1, 1>>>();
    amax_kernel<<<1536, 256>>>((const float4*)x, (const float4*)w);
    quant_kernel<<<5120, 256>>>((const float4*)x, (const float4*)w);

    dim3 grid(DOUT / BN, M_TOTAL / BM);  // (8, 64)
    gemm_kernel<<<grid, 512, GEMM_SMEM_BYTES>>>(out, bias);
}

// round 6
// speedup vs baseline: 1.2235x; 1.1139x over previous
#include <cuda_runtime.h>
#include <cuda_fp16.h>
#include <cstdint>

// ============================================================================
// Problem constants
// ============================================================================
#define M_TOTAL 8192   // B*S = 4*2048
#define DIN     2048
#define DOUT    2048
#define QDIV    358.4f // 448 * 0.8

// GEMM tiling (f16 carrier): 128x128 CTA tile, BK=64, 3 stages, 256 threads,
// 2 CTAs per SM.
#define BM 128
#define BN 128
#define BK 64
#define STAGES 3
#define NIT (DIN / BK)   // 32

// ============================================================================
// Device-global scratch (allocation-free requirement)
// ============================================================================
__device__ unsigned g_amax_x_bits;
__device__ unsigned g_amax_w_bits;
// fp8-rounded values stored as f16 (exact: e4m3 subset of f16)
__device__ __align__(128) __half g_qx[(size_t)M_TOTAL * DIN];   // 32 MB
__device__ __align__(128) __half g_qw[(size_t)DOUT * DIN];      //  8 MB

// ============================================================================
// Helpers
// ============================================================================
__device__ __forceinline__ uint32_t smem_to_u32(const void* p) {
    uint32_t a;
    asm("{ .reg .u64 t; cvta.to.shared.u64 t, %1; cvt.u32.u64 %0, t; }"
        : "=r"(a) : "l"(p));
    return a;
}

// fp32x2 -> packed e4m3x2 (RN, satfinite). low byte = lo, high byte = hi.
__device__ __forceinline__ uint16_t cvt_e4m3x2(float hi, float lo) {
    uint16_t r;
    asm("cvt.rn.satfinite.e4m3x2.f32 %0, %1, %2;" : "=h"(r) : "f"(hi), "f"(lo));
    return r;
}

// packed e4m3x2 -> f16x2 (exact)
__device__ __forceinline__ uint32_t cvt_f16x2_from_e4m3x2(uint16_t e) {
    uint32_t r;
    asm("cvt.rn.f16x2.e4m3x2 %0, %1;" : "=r"(r) : "h"(e));
    return r;
}

#define CP_ASYNC_16(dst, src) \
    asm volatile("cp.async.cg.shared.global [%0], [%1], 16;" \
                 :: "r"(dst), "l"(src))
#define CP_ASYNC_COMMIT() asm volatile("cp.async.commit_group;")
#define CP_ASYNC_WAIT_1() asm volatile("cp.async.wait_group 1;")

#define LDSM_X4(r, addr) \
    asm volatile("ldmatrix.sync.aligned.m8n8.x4.shared.b16 {%0,%1,%2,%3}, [%4];" \
        : "=r"((r)[0]), "=r"((r)[1]), "=r"((r)[2]), "=r"((r)[3]) : "r"(addr))

__device__ __forceinline__ void mma16816(float* d, const uint32_t* a,
                                         const uint32_t* b) {
    asm volatile(
        "mma.sync.aligned.m16n8k16.row.col.f32.f16.f16.f32 "
        "{%0,%1,%2,%3}, {%4,%5,%6,%7}, {%8,%9}, {%0,%1,%2,%3};"
        : "+f"(d[0]), "+f"(d[1]), "+f"(d[2]), "+f"(d[3])
        : "r"(a[0]), "r"(a[1]), "r"(a[2]), "r"(a[3]), "r"(b[0]), "r"(b[1]));
}

// SW128 swizzle for 128-byte rows (byte offsets)
__device__ __forceinline__ uint32_t swz(uint32_t off) {
    return off ^ ((off >> 3) & 0x70);
}

// div via reciprocal + one FMA residual refinement (== IEEE div for all but
// ~2^-40 of inputs; 3-mantissa-bit e4m3 RNE absorbs the rest)
__device__ __forceinline__ float div_cr(float x, float s, float inv) {
    float y = x * inv;
    float e = fmaf(-s, y, x);
    return fmaf(e, inv, y);
}

// ============================================================================
// Kernel 0: zero the amax scratch
// ============================================================================
__global__ void init_kernel() {
    g_amax_x_bits = 0u;
    g_amax_w_bits = 0u;
}

// ============================================================================
// Kernel 1: fused amax over x (blocks [0,1024)) and w (blocks [1024,1536))
// atomicMax on positive-float bits is order-exact.
// ============================================================================
__global__ void amax_kernel(const float4* __restrict__ x,
                            const float4* __restrict__ w) {
    const bool is_w = blockIdx.x >= 1024;
    const float4* p = is_w ? w : x;
    const int n4 = is_w ? (DOUT * DIN / 4) : (M_TOTAL * DIN / 4);
    const int nblk = is_w ? 512 : 1024;
    const int b0 = is_w ? 1024 : 0;
    float m = 0.0f;
    for (int i = (blockIdx.x - b0) * blockDim.x + threadIdx.x; i < n4;
         i += nblk * blockDim.x) {
        float4 v = p[i];
        m = fmaxf(m, fmaxf(fmaxf(fabsf(v.x), fabsf(v.y)),
                           fmaxf(fabsf(v.z), fabsf(v.w))));
    }
    #pragma unroll
    for (int o = 16; o; o >>= 1)
        m = fmaxf(m, __shfl_xor_sync(0xFFFFFFFFu, m, o));
    if ((threadIdx.x & 31) == 0)
        atomicMax(is_w ? &g_amax_w_bits : &g_amax_x_bits, __float_as_uint(m));
}

// ============================================================================
// Kernel 2: fused quantize x (blocks [0,4096)) and w (blocks [4096,5120)).
// Scales computed inline from the amax globals (deterministic recompute).
// Output: e4m3-rounded value stored exactly as f16.
// ============================================================================
__global__ void quant_kernel(const float4* __restrict__ x,
                             const float4* __restrict__ w) {
    const float ax = __uint_as_float(g_amax_x_bits);
    const float aw = __uint_as_float(g_amax_w_bits);
    const bool is_w = blockIdx.x >= 4096;
    const float s   = is_w ? (fmaxf(ax, aw) / QDIV) : (ax / QDIV);
    const float inv = 1.0f / s;
    const float4* p = is_w ? w : x;
    uint2* q = (uint2*)(is_w ? (void*)g_qw : (void*)g_qx);
    const int n4 = is_w ? (DOUT * DIN / 4) : (M_TOTAL * DIN / 4);
    const int nblk = is_w ? 1024 : 4096;
    const int b0 = is_w ? 4096 : 0;
    for (int i = (blockIdx.x - b0) * blockDim.x + threadIdx.x; i < n4;
         i += nblk * blockDim.x) {
        float4 v = p[i];
        float y0 = div_cr(v.x, s, inv);
        float y1 = div_cr(v.y, s, inv);
        float y2 = div_cr(v.z, s, inv);
        float y3 = div_cr(v.w, s, inv);
        uint2 o;
        o.x = cvt_f16x2_from_e4m3x2(cvt_e4m3x2(y1, y0));
        o.y = cvt_f16x2_from_e4m3x2(cvt_e4m3x2(y3, y2));
        q[i] = o;
    }
}

// ============================================================================
// Kernel 3: f16 HMMA GEMM. out[m,n] = (sum_k qx[m,k]*qw[n,k])*osc + bias[n]
// 128x128x64 CTA tile, 3-stage cp.async, SW128 swizzle, 2 CTAs/SM,
// 8 warps 2(M)x4(N), warp tile 64x32, m16n8k16,
// intra-stage fragment double buffering (LDSM s+1 overlaps MMA s).
// ============================================================================
#define STAGE_BYTES 32768                 // A 16KB + B 16KB
#define GEMM_SMEM_BYTES (STAGES * STAGE_BYTES)   // 98304

__global__ __launch_bounds__(256, 2) void gemm_kernel(
    float* __restrict__ out, const float* __restrict__ bias)
{
    extern __shared__ char smem[];
    const uint32_t sb = smem_to_u32(smem);
    const int tid  = threadIdx.x;
    const int lane = tid & 31;
    const int warp = tid >> 5;
    const int wm = warp >> 2;       // 0..1
    const int wn = warp & 3;        // 0..3
    const int nt = blockIdx.x;      // 0..15
    const int mt = blockIdx.y;      // 0..63

    const __half* gA = g_qx + (size_t)mt * BM * DIN;
    const __half* gB = g_qw + (size_t)nt * BN * DIN;

    // ---- per-thread cp.async chunk map: 4 chunks A + 4 chunks B per stage ----
    uint32_t dstA[4], dstB[4];
    const char* srcA[4];
    const char* srcB[4];
    #pragma unroll
    for (int q = 0; q < 4; ++q) {
        int ch  = tid + q * 256;
        int row = ch >> 3;
        int cb  = (ch & 7) * 16;
        uint32_t sw = swz((uint32_t)(row * 128 + cb));
        dstA[q] = sw;
        dstB[q] = 16384u + sw;
        srcA[q] = (const char*)(gA + (size_t)row * DIN) + cb;
        srcB[q] = (const char*)(gB + (size_t)row * DIN) + cb;
    }

    // ---- prologue: fill STAGES-1 stages ----
    int li = 0;
    #pragma unroll
    for (int s = 0; s < STAGES - 1; ++s) {
        uint32_t st = sb + s * STAGE_BYTES;
        #pragma unroll
        for (int q = 0; q < 4; ++q) {
            CP_ASYNC_16(st + dstA[q], srcA[q] + li * (BK * 2));
            CP_ASYNC_16(st + dstB[q], srcB[q] + li * (BK * 2));
        }
        CP_ASYNC_COMMIT();
        ++li;
    }
    CP_ASYNC_WAIT_1();
    __syncthreads();

    // ---- ldmatrix per-lane address components ----
    const int rA = wm * 64 + (lane & 7) + ((lane >> 3) & 1) * 8;
    const uint32_t cA0 = ((lane >> 4) & 1) * 16;
    const uint32_t xrA = (uint32_t)((rA & 7) << 4);
    const int rB = wn * 32 + (lane & 7) + ((lane >> 4) & 1) * 8;
    const uint32_t cB0 = ((lane >> 3) & 1) * 16;
    const uint32_t xrB = (uint32_t)((rB & 7) << 4);

    float acc[4][4][4];
    #pragma unroll
    for (int i = 0; i < 4; ++i)
        #pragma unroll
        for (int j = 0; j < 4; ++j)
            #pragma unroll
            for (int r = 0; r < 4; ++r) acc[i][j][r] = 0.0f;

    // double-buffered fragments
    uint32_t afr[2][4][4];
    uint32_t bfr[2][2][4];

    // ---- main loop ----
    #pragma unroll 1
    for (int it = 0; it < NIT; ++it) {
        const int cur = it % STAGES;
        if (li < NIT) {
            const int nx = (it + STAGES - 1) % STAGES;
            uint32_t st = sb + nx * STAGE_BYTES;
            #pragma unroll
            for (int q = 0; q < 4; ++q) {
                CP_ASYNC_16(st + dstA[q], srcA[q] + li * (BK * 2));
                CP_ASYNC_16(st + dstB[q], srcB[q] + li * (BK * 2));
            }
            ++li;
        }
        CP_ASYNC_COMMIT();

        const uint32_t stA = sb + cur * STAGE_BYTES;
        const uint32_t stB = stA + 16384;

        // preload k-step 0 fragments
        #pragma unroll
        for (int i = 0; i < 4; ++i)
            LDSM_X4(afr[0][i], stA + (uint32_t)((rA + i * 16) * 128) + (cA0 ^ xrA));
        #pragma unroll
        for (int jj = 0; jj < 2; ++jj)
            LDSM_X4(bfr[0][jj], stB + (uint32_t)((rB + jj * 16) * 128) + (cB0 ^ xrB));

        // k-steps: prefetch s+1 fragments, then issue MMAs for s
        #pragma unroll
        for (int s = 0; s < 4; ++s) {
            const int cb = s & 1, nb = cb ^ 1;
            if (s < 3) {
                #pragma unroll
                for (int i = 0; i < 4; ++i)
                    LDSM_X4(afr[nb][i], stA + (uint32_t)((rA + i * 16) * 128)
                                            + ((cA0 + (s + 1) * 32) ^ xrA));
                #pragma unroll
                for (int jj = 0; jj < 2; ++jj)
                    LDSM_X4(bfr[nb][jj], stB + (uint32_t)((rB + jj * 16) * 128)
                                             + ((cB0 + (s + 1) * 32) ^ xrB));
            }
            #pragma unroll
            for (int i = 0; i < 4; ++i)
                #pragma unroll
                for (int j = 0; j < 4; ++j)
                    mma16816(acc[i][j], afr[cb][i], bfr[cb][j >> 1] + (j & 1) * 2);
        }

        CP_ASYNC_WAIT_1();
        __syncthreads();
    }

    // ---- epilogue: osc from amax globals (deterministic), scale + bias ----
    const float ax = __uint_as_float(g_amax_x_bits);
    const float aw = __uint_as_float(g_amax_w_bits);
    const float osc = (ax / QDIV) * (fmaxf(ax, aw) / QDIV);
    const int m0 = mt * BM + wm * 64 + (lane >> 2);
    const int n0 = nt * BN + wn * 32 + (lane & 3) * 2;
    #pragma unroll
    for (int i = 0; i < 4; ++i) {
        #pragma unroll
        for (int j = 0; j < 4; ++j) {
            const int m = m0 + i * 16;
            const int n = n0 + j * 8;
            const float b0 = __ldg(&bias[n]);
            const float b1 = __ldg(&bias[n + 1]);
            float2 v0, v1;
            v0.x = fmaf(acc[i][j][0], osc, b0);
            v0.y = fmaf(acc[i][j][1], osc, b1);
            v1.x = fmaf(acc[i][j][2], osc, b0);
            v1.y = fmaf(acc[i][j][3], osc, b1);
            *(float2*)&out[(size_t)m * DOUT + n]       = v0;
            *(float2*)&out[(size_t)(m + 8) * DOUT + n] = v1;
        }
    }
}

// ============================================================================
// kernel_launch: 4 launches (init, amax, quant, gemm)
// ============================================================================
extern "C" void kernel_launch(void* const* d_in, const int* in_sizes, int n_in,
                              void* d_out, int out_size) {
    const float* x    = (const float*)d_in[0];   // [4,2048,2048]
    const float* w    = (const float*)d_in[1];   // [2048,2048]
    const float* bias = (const float*)d_in[2];   // [2048]
    float* out = (float*)d_out;

    static int smem_set = 0;
    if (!smem_set) {
        cudaFuncSetAttribute(gemm_kernel,
                             cudaFuncAttributeMaxDynamicSharedMemorySize,
                             GEMM_SMEM_BYTES);
        smem_set = 1;
    }

    init_kernel<<<1, 1>>>();
    amax_kernel<<<1536, 256>>>((const float4*)x, (const float4*)w);
    quant_kernel<<<5120, 256>>>((const float4*)x, (const float4*)w);

    dim3 grid(DOUT / BN, M_TOTAL / BM);  // (16, 64)
    gemm_kernel<<<grid, 256, GEMM_SMEM_BYTES>>>(out, bias);
}